// round 8
// baseline (speedup 1.0000x reference)
#include <cuda_runtime.h>
#include <cstdint>

// out[n,w,i] = (1/m) * sum_u x[n,u,i] * weight[n,u] * W[u,w]
// Irreps: 256x0e + 128x1o + 64x2e + 32x3o ; DIM=1184, WNUM=480
// R8: vectorized fill stores. d>1: junk-padded STS.128/64 per u-slot.
//     d=1 (b0): transposed A tile As[row][k] -> STS.128 fill, float4-along-k frags.

#define DIM_ 1184
#define WNUM_ 480
typedef unsigned long long ull;

__device__ __forceinline__ void cp_async16(uint32_t dst, const void* src) {
    asm volatile("cp.async.cg.shared.global [%0], [%1], 16;" :: "r"(dst), "l"(src));
}
__device__ __forceinline__ void cp_commit() { asm volatile("cp.async.commit_group;"); }
__device__ __forceinline__ void cp_wait0()  { asm volatile("cp.async.wait_group 0;" ::: "memory"); }

#define SMEM_BYTES 43264

// ------------------------- d == 1 (b0) specialization -------------------------
// As transposed: As[2][BN][BK+4]; fill = vec4; A-frag = float4 along k.
template<int M, int BN, int BW, int BK, int TN, int TW>
__device__ __forceinline__
void run_tp_d1(char* smraw,
               const float* __restrict__ x, const float* __restrict__ wt,
               const float* __restrict__ Wm, float* __restrict__ out,
               int n0, int nrows, int xo, int wo)
{
    constexpr int NT  = 256;
    constexpr int THW = BW / TW;       // 32
    constexpr int THN = BN / TN;       // 8
    static_assert(THW * THN == NT, "grid");
    constexpr int RT  = NT / BN;       // 4
    constexpr int KPT = BK / RT;       // 4
    static_assert(KPT == 4, "vec4 fill");
    constexpr int ROWK = BK + 4;       // 20 floats per row
    constexpr int TILES = M / BK;
    constexpr int NB4 = BK * BW / 4;
    constexpr int AS_BYTES = 2 * BN * ROWK * 4;
    static_assert(AS_BYTES + 2 * BK * BW * 4 <= SMEM_BYTES, "smem");

    float (*As)[BN][ROWK] = reinterpret_cast<float (*)[BN][ROWK]>(smraw);
    float (*Bs)[BK][BW]   = reinterpret_cast<float (*)[BK][BW]>(smraw + AS_BYTES);

    const int tid = threadIdx.x;
    const int twi = tid % THW;
    const int tni = tid / THW;
    const int tn0 = tni * TN;
    const int rf  = tid / RT;
    const int q   = tid % RT;
    const bool rvalid = (n0 + rf) < nrows;
    const float inv_m = 1.0f / (float)M;

    const float* xrow = x  + (size_t)(n0 + rf) * DIM_  + xo + q * KPT;
    const float* wrow = wt + (size_t)(n0 + rf) * WNUM_ + wo + q * KPT;
    const uint32_t bs0 = (uint32_t)__cvta_generic_to_shared(&Bs[0][0][0]);

    ull acc[TN][TW / 2];
#pragma unroll
    for (int e = 0; e < TN; ++e)
#pragma unroll
        for (int j2 = 0; j2 < TW / 2; ++j2) acc[e][j2] = 0ull;

    float4 xr, wr;

    auto ld_regs = [&](int u0) {
        if (rvalid) {
            xr = *reinterpret_cast<const float4*>(xrow + u0);
            wr = *reinterpret_cast<const float4*>(wrow + u0);
        } else {
            xr = make_float4(0.f, 0.f, 0.f, 0.f);
            wr = xr;
        }
    };

    auto ld_bs = [&](int u0, int buf) {
        const float4* src = reinterpret_cast<const float4*>(Wm + (size_t)u0 * M);
        uint32_t dst = bs0 + (uint32_t)buf * (BK * BW * 4);
#pragma unroll
        for (int v = 0; v < NB4 / NT; ++v)
            cp_async16(dst + (tid + v * NT) * 16, src + tid + v * NT);
    };

    auto st_as = [&](int buf) {
        float4 f = make_float4(xr.x * (wr.x * inv_m), xr.y * (wr.y * inv_m),
                               xr.z * (wr.z * inv_m), xr.w * (wr.w * inv_m));
        *reinterpret_cast<float4*>(&As[buf][rf][q * 4]) = f;
    };

    auto compute = [&](int buf) {
#pragma unroll
        for (int k4 = 0; k4 < BK; k4 += 4) {
            float4 af4[TN];
#pragma unroll
            for (int a = 0; a < TN; ++a)
                af4[a] = *reinterpret_cast<const float4*>(&As[buf][tn0 + a][k4]);
#pragma unroll
            for (int kk = 0; kk < 4; ++kk) {
                ull bf[TW / 2];
                const ull* bp = reinterpret_cast<const ull*>(&Bs[buf][k4 + kk][0]);
#pragma unroll
                for (int j2 = 0; j2 < TW / 2; ++j2) bf[j2] = bp[twi + j2 * THW];
#pragma unroll
                for (int a = 0; a < TN; ++a) {
                    float av = (kk == 0) ? af4[a].x : (kk == 1) ? af4[a].y
                             : (kk == 2) ? af4[a].z : af4[a].w;
                    ull a2;
                    asm("mov.b64 %0, {%1, %1};" : "=l"(a2) : "r"(__float_as_uint(av)));
#pragma unroll
                    for (int j2 = 0; j2 < TW / 2; ++j2)
                        asm("fma.rn.f32x2 %0, %1, %2, %0;"
                            : "+l"(acc[a][j2]) : "l"(a2), "l"(bf[j2]));
                }
            }
        }
    };

    ld_regs(0);
    ld_bs(0, 0);
    cp_commit();
    st_as(0);
    cp_wait0();
    __syncthreads();

#pragma unroll 1
    for (int t = 0; t < TILES; ++t) {
        const int cur = t & 1;
        if (t + 1 < TILES) {
            ld_regs((t + 1) * BK);
            ld_bs((t + 1) * BK, cur ^ 1);
            cp_commit();
        }
        compute(cur);
        if (t + 1 < TILES) {
            st_as(cur ^ 1);
            cp_wait0();
        }
        __syncthreads();
    }

#pragma unroll
    for (int a = 0; a < TN; ++a) {
        int gn = n0 + tn0 + a;
        if (gn >= nrows) continue;
        float* orow = out + (size_t)gn * DIM_ + xo;
#pragma unroll
        for (int j2 = 0; j2 < TW / 2; ++j2) {
            int wlo = twi * 2 + j2 * 2 * THW;
            ull v = acc[a][j2];
            float2 p = make_float2(__uint_as_float((uint32_t)(v & 0xffffffffull)),
                                   __uint_as_float((uint32_t)(v >> 32)));
            *reinterpret_cast<float2*>(orow + wlo) = p;
        }
    }
}

// ------------------------- d > 1 generic -------------------------
template<int D, int DP, int M, int BN, int BW, int BK, int TN, int TW>
__device__ __forceinline__
void run_tp(char* smraw,
            const float* __restrict__ x, const float* __restrict__ wt,
            const float* __restrict__ Wm, float* __restrict__ out,
            int n0, int nrows, int xo, int wo)
{
    constexpr int NT  = 256;
    constexpr int THW = BW / TW;
    constexpr int THN = BN / TN;
    static_assert(THW * THN == NT, "grid");
    constexpr int RT  = NT / BN;
    constexpr int KPT = BK / RT;
    constexpr int CPT = KPT * D;
    constexpr int AFP = TN * DP;
    constexpr int ROWLEN = BN * DP + 4;
    static_assert(ROWLEN % 4 == 0, "rowpad");
    static_assert(AFP % 4 == 0, "afrag");
    constexpr int TILES = M / BK;
    constexpr int NB4 = BK * BW / 4;
    constexpr int AS_BYTES = 2 * BK * ROWLEN * 4;
    static_assert(AS_BYTES + 2 * BK * BW * 4 <= SMEM_BYTES, "smem");

    float (*As)[BK][ROWLEN] = reinterpret_cast<float (*)[BK][ROWLEN]>(smraw);
    float (*Bs)[BK][BW]     = reinterpret_cast<float (*)[BK][BW]>(smraw + AS_BYTES);

    const int tid = threadIdx.x;
    const int twi = tid % THW;
    const int tni = tid / THW;
    const int rf  = tid / RT;
    const int q   = tid % RT;
    const bool rvalid = (n0 + rf) < nrows;
    const float inv_m = 1.0f / (float)M;

    const float* xrow = x  + (size_t)(n0 + rf) * DIM_  + xo + q * CPT;
    const float* wrow = wt + (size_t)(n0 + rf) * WNUM_ + wo + q * KPT;
    const uint32_t bs0 = (uint32_t)__cvta_generic_to_shared(&Bs[0][0][0]);

    ull acc[TN * D][TW / 2];
#pragma unroll
    for (int e = 0; e < TN * D; ++e)
#pragma unroll
        for (int j2 = 0; j2 < TW / 2; ++j2) acc[e][j2] = 0ull;

    alignas(16) float xr[CPT];
    alignas(8)  float wr[KPT];

    auto ld_regs = [&](int u0) {
        if (rvalid) {
            const float* xp = xrow + (size_t)u0 * D;
            if constexpr (CPT % 4 == 0) {
#pragma unroll
                for (int v = 0; v < CPT / 4; ++v)
                    reinterpret_cast<float4*>(xr)[v] =
                        reinterpret_cast<const float4*>(xp)[v];
            } else {
#pragma unroll
                for (int v = 0; v < CPT / 2; ++v)
                    reinterpret_cast<float2*>(xr)[v] =
                        reinterpret_cast<const float2*>(xp)[v];
            }
            const float* wp = wrow + u0;
            if constexpr (KPT % 2 == 0) {
#pragma unroll
                for (int v = 0; v < KPT / 2; ++v)
                    reinterpret_cast<float2*>(wr)[v] =
                        reinterpret_cast<const float2*>(wp)[v];
            } else {
#pragma unroll
                for (int v = 0; v < KPT; ++v) wr[v] = wp[v];
            }
        } else {
#pragma unroll
            for (int j = 0; j < CPT; ++j) xr[j] = 0.0f;
#pragma unroll
            for (int j = 0; j < KPT; ++j) wr[j] = 0.0f;
        }
    };

    auto ld_bs = [&](int u0, int buf) {
        const float4* src = reinterpret_cast<const float4*>(Wm + (size_t)u0 * M);
        uint32_t dst = bs0 + (uint32_t)buf * (BK * BW * 4);
#pragma unroll
        for (int v = 0; v < (NB4 + NT - 1) / NT; ++v) {
            int idx = tid + v * NT;
            if ((NB4 % NT == 0) || idx < NB4)
                cp_async16(dst + idx * 16, src + idx);
        }
    };

    // vectorized fill: per u-slot, DP-wide store with scale value in pad lane
    auto st_as = [&](int buf) {
#pragma unroll
        for (int u = 0; u < KPT; ++u) {
            const int kk = q * KPT + u;
            const float ws = wr[u] * inv_m;
            float* dst = &As[buf][kk][rf * DP];
            if constexpr (D == 3) {
                float4 f = make_float4(xr[u*3+0]*ws, xr[u*3+1]*ws, xr[u*3+2]*ws, ws);
                *reinterpret_cast<float4*>(dst) = f;
            } else if constexpr (D == 5) {
                *reinterpret_cast<float2*>(dst + 0) = make_float2(xr[u*5+0]*ws, xr[u*5+1]*ws);
                *reinterpret_cast<float2*>(dst + 2) = make_float2(xr[u*5+2]*ws, xr[u*5+3]*ws);
                *reinterpret_cast<float2*>(dst + 4) = make_float2(xr[u*5+4]*ws, ws);
            } else { // D == 7
                float4 f0 = make_float4(xr[u*7+0]*ws, xr[u*7+1]*ws, xr[u*7+2]*ws, xr[u*7+3]*ws);
                float4 f1 = make_float4(xr[u*7+4]*ws, xr[u*7+5]*ws, xr[u*7+6]*ws, ws);
                *reinterpret_cast<float4*>(dst + 0) = f0;
                *reinterpret_cast<float4*>(dst + 4) = f1;
            }
        }
    };

    auto compute = [&](int buf) {
#pragma unroll
        for (int k = 0; k < BK; ++k) {
            alignas(16) float af[AFP];
            const float* ap = &As[buf][k][tni * TN * DP];
#pragma unroll
            for (int v = 0; v < AFP / 4; ++v)
                reinterpret_cast<float4*>(af)[v] =
                    reinterpret_cast<const float4*>(ap)[v];

            ull bf[TW / 2];
            const ull* bp = reinterpret_cast<const ull*>(&Bs[buf][k][0]);
#pragma unroll
            for (int j2 = 0; j2 < TW / 2; ++j2) bf[j2] = bp[twi + j2 * THW];

#pragma unroll
            for (int a = 0; a < TN; ++a)
#pragma unroll
                for (int i = 0; i < D; ++i) {
                    ull a2;
                    asm("mov.b64 %0, {%1, %1};"
                        : "=l"(a2) : "r"(__float_as_uint(af[a * DP + i])));
#pragma unroll
                    for (int j2 = 0; j2 < TW / 2; ++j2)
                        asm("fma.rn.f32x2 %0, %1, %2, %0;"
                            : "+l"(acc[a * D + i][j2]) : "l"(a2), "l"(bf[j2]));
                }
        }
    };

    ld_regs(0);
    ld_bs(0, 0);
    cp_commit();
    st_as(0);
    cp_wait0();
    __syncthreads();

#pragma unroll 1
    for (int t = 0; t < TILES; ++t) {
        const int cur = t & 1;
        if (t + 1 < TILES) {
            ld_regs((t + 1) * BK);
            ld_bs((t + 1) * BK, cur ^ 1);
            cp_commit();
        }
        compute(cur);
        if (t + 1 < TILES) {
            st_as(cur ^ 1);
            cp_wait0();
        }
        __syncthreads();
    }

#pragma unroll
    for (int a = 0; a < TN; ++a) {
        int gn = n0 + tni * TN + a;
        if (gn >= nrows) continue;
        float* orow = out + (size_t)gn * DIM_ + xo;
#pragma unroll
        for (int j2 = 0; j2 < TW / 2; ++j2) {
            int wlo = twi * 2 + j2 * 2 * THW;
#pragma unroll
            for (int i = 0; i < D; ++i) {
                ull v = acc[a * D + i][j2];
                float lo = __uint_as_float((uint32_t)(v & 0xffffffffull));
                float hi = __uint_as_float((uint32_t)(v >> 32));
                orow[(size_t)wlo * D + i]       = lo;
                orow[(size_t)(wlo + 1) * D + i] = hi;
            }
        }
    }
}

// chunk pattern of 6 blocks per 64 rows: {b0(64), b1(32)x2, b2(32)x2, b3(64)}
__global__ __launch_bounds__(256, 2)
void tp_fused_kernel(const float* __restrict__ x, const float* __restrict__ wt,
                     const float* __restrict__ W0, const float* __restrict__ W1,
                     const float* __restrict__ W2, const float* __restrict__ W3,
                     float* __restrict__ out, int nrows)
{
    __shared__ alignas(16) char smraw[SMEM_BYTES];
    const int bid = blockIdx.x;
    const int r = bid / 6;
    const int t = bid - r * 6;

    if (t == 0) {
        // b0: m=256, d=1 | BN=64, BW=256, BK=16, TN=8, TW=8 (transposed A)
        run_tp_d1<256, 64, 256, 16, 8, 8>(smraw, x, wt, W0, out,
                                          r * 64, nrows, 0, 0);
    } else if (t <= 2) {
        // b1: m=128, d=3 (DP=4) | BN=32, BW=128, BK=16, TN=2, TW=8
        run_tp<3, 4, 128, 32, 128, 16, 2, 8>(smraw, x, wt, W1, out,
                                             (2 * r + (t - 1)) * 32, nrows, 256, 256);
    } else if (t <= 4) {
        // b2: m=64, d=5 (DP=6) | BN=32, BW=64, BK=16, TN=2, TW=4
        run_tp<5, 6, 64, 32, 64, 16, 2, 4>(smraw, x, wt, W2, out,
                                           (2 * r + (t - 3)) * 32, nrows, 640, 384);
    } else {
        // b3: m=32, d=7 (DP=8) | BN=64, BW=32, BK=8, TN=2, TW=4
        run_tp<7, 8, 32, 64, 32, 8, 2, 4>(smraw, x, wt, W3, out,
                                          r * 64, nrows, 960, 448);
    }
}

extern "C" void kernel_launch(void* const* d_in, const int* in_sizes, int n_in,
                              void* d_out, int out_size)
{
    const float* x  = (const float*)d_in[0];
    const float* wtp = (const float*)d_in[1];
    const float* W0 = (const float*)d_in[2];
    const float* W1 = (const float*)d_in[3];
    const float* W2 = (const float*)d_in[4];
    const float* W3 = (const float*)d_in[5];
    float* out = (float*)d_out;

    const int nrows = in_sizes[0] / DIM_;
    const int nchunk = (nrows + 63) / 64;
    tp_fused_kernel<<<nchunk * 6, 256>>>(x, wtp, W0, W1, W2, W3, out, nrows);
}

// round 10
// speedup vs baseline: 1.9032x; 1.9032x over previous
#include <cuda_runtime.h>
#include <cuda_bf16.h>
#include <cstdint>

// out[n,w,i] = (1/m) * sum_u x[n,u,i] * weight[n,u] * W[u,w]
// Irreps: 256x0e + 128x1o + 64x2e + 32x3o ; DIM=1184, WNUM=480
// R10: warp-level mma.sync bf16 split-precision (3-term) GEMM.
//      B split precomputed once to __device__ scratch; A split fused in fill.

#define DIM_ 1184
#define WNUM_ 480
typedef unsigned long long ull;

// B split scratch: hi plane [0,87040), lo plane [87040,174080) bf16
// matrix offsets (bf16 elems): W0:0  W1:65536  W2:81920  W3:86016
__device__ __align__(16) __nv_bfloat16 g_bsplit[2 * 87040];

__device__ __forceinline__ void split2(float s0, float s1, uint32_t& h, uint32_t& l) {
    asm("cvt.rn.satfinite.bf16x2.f32 %0, %1, %2;" : "=r"(h) : "f"(s1), "f"(s0));
    float h0 = __uint_as_float(h << 16);
    float h1 = __uint_as_float(h & 0xffff0000u);
    asm("cvt.rn.satfinite.bf16x2.f32 %0, %1, %2;" : "=r"(l) : "f"(s1 - h1), "f"(s0 - h0));
}

__device__ __forceinline__ void cp_async16(uint32_t dst, const void* src) {
    asm volatile("cp.async.cg.shared.global [%0], [%1], 16;" :: "r"(dst), "l"(src));
}
__device__ __forceinline__ void cp_commit() { asm volatile("cp.async.commit_group;"); }
__device__ __forceinline__ void cp_wait0()  { asm volatile("cp.async.wait_group 0;" ::: "memory"); }

__device__ __forceinline__ void ldsm4(uint32_t* r, uint32_t a) {
    asm volatile("ldmatrix.sync.aligned.m8n8.x4.shared.b16 {%0,%1,%2,%3}, [%4];"
                 : "=r"(r[0]), "=r"(r[1]), "=r"(r[2]), "=r"(r[3]) : "r"(a));
}
__device__ __forceinline__ void ldsm4t(uint32_t* r, uint32_t a) {
    asm volatile("ldmatrix.sync.aligned.m8n8.x4.trans.shared.b16 {%0,%1,%2,%3}, [%4];"
                 : "=r"(r[0]), "=r"(r[1]), "=r"(r[2]), "=r"(r[3]) : "r"(a));
}
__device__ __forceinline__ void mma16816(float* c, const uint32_t* a,
                                         uint32_t b0, uint32_t b1) {
    asm volatile(
        "mma.sync.aligned.m16n8k16.row.col.f32.bf16.bf16.f32 "
        "{%0,%1,%2,%3}, {%4,%5,%6,%7}, {%8,%9}, {%0,%1,%2,%3};"
        : "+f"(c[0]), "+f"(c[1]), "+f"(c[2]), "+f"(c[3])
        : "r"(a[0]), "r"(a[1]), "r"(a[2]), "r"(a[3]), "r"(b0), "r"(b1));
}

// ---------------- B split precompute ----------------
__global__ void split_b_kernel(const float* __restrict__ W0, const float* __restrict__ W1,
                               const float* __restrict__ W2, const float* __restrict__ W3)
{
    int idx = blockIdx.x * blockDim.x + threadIdx.x;   // pair index
    if (idx >= 43520) return;
    int e = idx * 2;
    const float* src; int off;
    if (e < 65536)      { src = W0; off = e; }
    else if (e < 81920) { src = W1; off = e - 65536; }
    else if (e < 86016) { src = W2; off = e - 81920; }
    else                { src = W3; off = e - 86016; }
    float2 v = *reinterpret_cast<const float2*>(src + off);
    uint32_t h, l;
    split2(v.x, v.y, h, l);
    reinterpret_cast<uint32_t*>(g_bsplit)[idx] = h;
    reinterpret_cast<uint32_t*>(g_bsplit)[43520 + idx] = l;
}

// ---------------- GEMM per irrep block ----------------
// D irrep dim; M multiplicity (=K=N); ROWS GEMM rows per CTA; NU n-rows;
// WR x WC warp grid (8 warps).
template<int D, int M, int ROWS, int NU, int WR, int WC>
__global__ __launch_bounds__(256, 2)
void tp_mma_kernel(const float* __restrict__ x, const float* __restrict__ wt,
                   float* __restrict__ out, int nrows, int xo, int wo, int moff)
{
    constexpr int BK  = 16;
    constexpr int TR  = ROWS / WR, TC = M / WC;
    constexpr int MR  = TR / 16,   MC = TC / 8;
    static_assert(WR * WC == 8 && MR >= 1 && (MC % 2) == 0, "warp grid");
    constexpr int SA  = BK + 8;              // A smem stride (bf16)
    constexpr int SB  = M + 8;               // B smem stride (bf16)
    constexpr int KT  = M / BK;              // k tiles
    constexpr int PT  = 256 / ROWS;          // fill threads per row
    constexpr int EPT = BK / PT;             // elems per fill thread
    constexpr int NP  = EPT / 2;             // pairs per fill thread
    static_assert(D != 1 || EPT == 4, "b0 fill");
    static_assert(EPT % 4 == 0, "wt vec4");

    __shared__ __align__(16) __nv_bfloat16 As[2][2][ROWS][SA];
    __shared__ __align__(16) __nv_bfloat16 Bs[2][2][BK][SB];

    const int tid = threadIdx.x, lane = tid & 31, wid = tid >> 5;
    const int warpR = wid % WR, warpC = wid / WR;
    const int rw0 = warpR * TR, c0w = warpC * TC;
    const int n0 = blockIdx.x * NU;
    const float inv_m = 1.0f / (float)M;

    // ---- fill thread ids ----
    const int rfill = tid / PT;
    const int kbase = (tid % PT) * EPT;
    const int nl_f = rfill / D, i_f = rfill - nl_f * D;
    const bool fvalid = (rfill < NU * D) && ((n0 + nl_f) < nrows);
    const float* xrow = x  + (size_t)(n0 + nl_f) * DIM_  + xo + i_f;
    const float* wrow = wt + (size_t)(n0 + nl_f) * WNUM_ + wo;

    const uint32_t smA = (uint32_t)__cvta_generic_to_shared(&As[0][0][0][0]);
    const uint32_t smB = (uint32_t)__cvta_generic_to_shared(&Bs[0][0][0][0]);
    constexpr uint32_t PS_A = ROWS * SA * 2, BS_A = 2 * PS_A;
    constexpr uint32_t PS_B = BK * SB * 2,   BS_B = 2 * PS_B;

    // ldsm lane addresses
    const uint32_t aAddr0 = smA +
        (uint32_t)(((rw0 + (lane & 15)) * SA + ((lane >> 4) << 3)) * 2);
    const int bg = lane >> 3;
    const uint32_t bAddr0 = smB +
        (uint32_t)(((((bg & 1) << 3) + (lane & 7)) * SB + c0w + ((bg >> 1) << 3)) * 2);

    float acc[MR][MC][4];
#pragma unroll
    for (int a = 0; a < MR; ++a)
#pragma unroll
        for (int b = 0; b < MC; ++b)
#pragma unroll
            for (int c = 0; c < 4; ++c) acc[a][b][c] = 0.0f;

    float xr[EPT], wr[EPT];

    auto ld_regs = [&](int k0) {
        if (fvalid) {
            if constexpr (D == 1) {
                *reinterpret_cast<float4*>(xr) =
                    *reinterpret_cast<const float4*>(xrow + k0 + kbase);
            } else {
#pragma unroll
                for (int j = 0; j < EPT; ++j)
                    xr[j] = xrow[(size_t)(k0 + kbase + j) * D];
            }
#pragma unroll
            for (int v = 0; v < EPT / 4; ++v)
                reinterpret_cast<float4*>(wr)[v] =
                    *reinterpret_cast<const float4*>(wrow + k0 + kbase + 4 * v);
        } else {
#pragma unroll
            for (int j = 0; j < EPT; ++j) { xr[j] = 0.0f; wr[j] = 0.0f; }
        }
    };

    auto st_as = [&](int buf) {
        uint32_t hh[NP], ll[NP];
#pragma unroll
        for (int p = 0; p < NP; ++p) {
            float s0 = xr[2 * p]     * (wr[2 * p]     * inv_m);
            float s1 = xr[2 * p + 1] * (wr[2 * p + 1] * inv_m);
            split2(s0, s1, hh[p], ll[p]);
        }
        ull* dh = reinterpret_cast<ull*>(&As[buf][0][rfill][kbase]);
        ull* dl = reinterpret_cast<ull*>(&As[buf][1][rfill][kbase]);
#pragma unroll
        for (int q = 0; q < NP / 2; ++q) {
            dh[q] = (ull)hh[2 * q] | ((ull)hh[2 * q + 1] << 32);
            dl[q] = (ull)ll[2 * q] | ((ull)ll[2 * q + 1] << 32);
        }
    };

    auto ld_bs = [&](int k0, int buf) {
        constexpr int SEGS = M / 8;               // 16B chunks per k-row
        constexpr int CHT  = 2 * BK * SEGS;       // total chunks
        const char* gsrc = reinterpret_cast<const char*>(g_bsplit);
#pragma unroll
        for (int c = tid; c < CHT; c += 256) {
            int plane = c / (BK * SEGS);
            int rem   = c - plane * (BK * SEGS);
            int k     = rem / SEGS;
            int sg    = rem - k * SEGS;
            uint32_t dst = smB + (uint32_t)buf * BS_B + (uint32_t)plane * PS_B
                         + (uint32_t)((k * SB + sg * 8) * 2);
            const char* src = gsrc +
                (size_t)(plane * 87040 + moff + (k0 + k) * M + sg * 8) * 2;
            cp_async16(dst, src);
        }
    };

    auto compute = [&](int buf) {
        uint32_t ah[MR][4], al[MR][4];
#pragma unroll
        for (int mr = 0; mr < MR; ++mr) {
            uint32_t a = aAddr0 + (uint32_t)buf * BS_A + (uint32_t)(mr * 16 * SA * 2);
            ldsm4(ah[mr], a);
            ldsm4(al[mr], a + PS_A);
        }
#pragma unroll
        for (int mc2 = 0; mc2 < MC / 2; ++mc2) {
            uint32_t b = bAddr0 + (uint32_t)buf * BS_B + (uint32_t)(mc2 * 32);
            uint32_t bh[4], bl[4];
            ldsm4t(bh, b);
            ldsm4t(bl, b + PS_B);
#pragma unroll
            for (int mr = 0; mr < MR; ++mr) {
                mma16816(acc[mr][2 * mc2],     ah[mr], bh[0], bh[1]);
                mma16816(acc[mr][2 * mc2],     ah[mr], bl[0], bl[1]);
                mma16816(acc[mr][2 * mc2],     al[mr], bh[0], bh[1]);
                mma16816(acc[mr][2 * mc2 + 1], ah[mr], bh[2], bh[3]);
                mma16816(acc[mr][2 * mc2 + 1], ah[mr], bl[2], bl[3]);
                mma16816(acc[mr][2 * mc2 + 1], al[mr], bh[2], bh[3]);
            }
        }
    };

    // ---- pipeline ----
    ld_regs(0);
    ld_bs(0, 0);
    cp_commit();
    st_as(0);
    cp_wait0();
    __syncthreads();

#pragma unroll 1
    for (int t = 0; t < KT; ++t) {
        const int cur = t & 1;
        if (t + 1 < KT) {
            ld_regs((t + 1) * BK);
            ld_bs((t + 1) * BK, cur ^ 1);
            cp_commit();
        }
        compute(cur);
        if (t + 1 < KT) {
            st_as(cur ^ 1);
            cp_wait0();
        }
        __syncthreads();
    }

    // ---- epilogue: direct STG from mma fragments ----
#pragma unroll
    for (int mr = 0; mr < MR; ++mr) {
#pragma unroll
        for (int half = 0; half < 2; ++half) {
            const int r = rw0 + mr * 16 + (lane >> 2) + half * 8;
            if (r < NU * D) {
                const int nl = r / D, i = r - nl * D;
                const int n = n0 + nl;
                if (n < nrows) {
                    float* orow = out + (size_t)n * DIM_ + xo;
#pragma unroll
                    for (int mc = 0; mc < MC; ++mc) {
                        const int cw = c0w + mc * 8 + 2 * (lane & 3);
                        const float v0 = acc[mr][mc][half * 2];
                        const float v1 = acc[mr][mc][half * 2 + 1];
                        if constexpr (D == 1) {
                            *reinterpret_cast<float2*>(orow + cw) = make_float2(v0, v1);
                        } else {
                            orow[(size_t)cw * D + i]       = v0;
                            orow[(size_t)(cw + 1) * D + i] = v1;
                        }
                    }
                }
            }
        }
    }
}

// ---------------- launch ----------------
extern "C" void kernel_launch(void* const* d_in, const int* in_sizes, int n_in,
                              void* d_out, int out_size)
{
    const float* x  = (const float*)d_in[0];
    const float* wtp = (const float*)d_in[1];
    const float* W0 = (const float*)d_in[2];
    const float* W1 = (const float*)d_in[3];
    const float* W2 = (const float*)d_in[4];
    const float* W3 = (const float*)d_in[5];
    float* out = (float*)d_out;

    const int nrows = in_sizes[0] / DIM_;

    split_b_kernel<<<170, 256>>>(W0, W1, W2, W3);

    // b0: m=256 d=1 | CTA 64rows x 256cols, warps 2x4 (warp 32x64)
    tp_mma_kernel<1, 256, 64, 64, 2, 4>
        <<<(nrows + 63) / 64, 256>>>(x, wtp, out, nrows, 0, 0, 0);
    // b1: m=128 d=3 | CTA 128x128, warps 4x2 (warp 32x64)
    tp_mma_kernel<3, 128, 128, 42, 4, 2>
        <<<(nrows + 41) / 42, 256>>>(x, wtp, out, nrows, 256, 256, 65536);
    // b2: m=64 d=5 | CTA 128x64, warps 4x2 (warp 32x32)
    tp_mma_kernel<5, 64, 128, 25, 4, 2>
        <<<(nrows + 24) / 25, 256>>>(x, wtp, out, nrows, 640, 384, 81920);
    // b3: m=32 d=7 | CTA 128x32, warps 8x1 (warp 16x32)
    tp_mma_kernel<7, 32, 128, 18, 8, 1>
        <<<(nrows + 17) / 18, 256>>>(x, wtp, out, nrows, 960, 448, 86016);
}

// round 11
// speedup vs baseline: 1.9103x; 1.0037x over previous
#include <cuda_runtime.h>
#include <cuda_bf16.h>
#include <cstdint>

// out[n,w,i] = (1/m) * sum_u x[n,u,i] * weight[n,u] * W[u,w]
// Irreps: 256x0e + 128x1o + 64x2e + 32x3o ; DIM=1184, WNUM=480
// R11: fused single-launch mma.sync bf16 split-precision (3-term) GEMMs.

#define DIM_ 1184
#define WNUM_ 480
typedef unsigned long long ull;

// B split scratch: hi plane [0,87040), lo plane [87040,174080) bf16
__device__ __align__(16) __nv_bfloat16 g_bsplit[2 * 87040];

__device__ __forceinline__ void split2(float s0, float s1, uint32_t& h, uint32_t& l) {
    asm("cvt.rn.satfinite.bf16x2.f32 %0, %1, %2;" : "=r"(h) : "f"(s1), "f"(s0));
    float h0 = __uint_as_float(h << 16);
    float h1 = __uint_as_float(h & 0xffff0000u);
    asm("cvt.rn.satfinite.bf16x2.f32 %0, %1, %2;" : "=r"(l) : "f"(s1 - h1), "f"(s0 - h0));
}

__device__ __forceinline__ void cp_async16(uint32_t dst, const void* src) {
    asm volatile("cp.async.cg.shared.global [%0], [%1], 16;" :: "r"(dst), "l"(src));
}
__device__ __forceinline__ void cp_commit() { asm volatile("cp.async.commit_group;"); }
__device__ __forceinline__ void cp_wait0()  { asm volatile("cp.async.wait_group 0;" ::: "memory"); }

__device__ __forceinline__ void ldsm4(uint32_t* r, uint32_t a) {
    asm volatile("ldmatrix.sync.aligned.m8n8.x4.shared.b16 {%0,%1,%2,%3}, [%4];"
                 : "=r"(r[0]), "=r"(r[1]), "=r"(r[2]), "=r"(r[3]) : "r"(a));
}
__device__ __forceinline__ void ldsm4t(uint32_t* r, uint32_t a) {
    asm volatile("ldmatrix.sync.aligned.m8n8.x4.trans.shared.b16 {%0,%1,%2,%3}, [%4];"
                 : "=r"(r[0]), "=r"(r[1]), "=r"(r[2]), "=r"(r[3]) : "r"(a));
}
__device__ __forceinline__ void mma16816(float* c, const uint32_t* a,
                                         uint32_t b0, uint32_t b1) {
    asm volatile(
        "mma.sync.aligned.m16n8k16.row.col.f32.bf16.bf16.f32 "
        "{%0,%1,%2,%3}, {%4,%5,%6,%7}, {%8,%9}, {%0,%1,%2,%3};"
        : "+f"(c[0]), "+f"(c[1]), "+f"(c[2]), "+f"(c[3])
        : "r"(a[0]), "r"(a[1]), "r"(a[2]), "r"(a[3]), "r"(b0), "r"(b1));
}

// ---------------- B split precompute ----------------
__global__ void split_b_kernel(const float* __restrict__ W0, const float* __restrict__ W1,
                               const float* __restrict__ W2, const float* __restrict__ W3)
{
    int idx = blockIdx.x * blockDim.x + threadIdx.x;
    if (idx >= 43520) return;
    int e = idx * 2;
    const float* src; int off;
    if (e < 65536)      { src = W0; off = e; }
    else if (e < 81920) { src = W1; off = e - 65536; }
    else if (e < 86016) { src = W2; off = e - 81920; }
    else                { src = W3; off = e - 86016; }
    float2 v = *reinterpret_cast<const float2*>(src + off);
    uint32_t h, l;
    split2(v.x, v.y, h, l);
    reinterpret_cast<uint32_t*>(g_bsplit)[idx] = h;
    reinterpret_cast<uint32_t*>(g_bsplit)[43520 + idx] = l;
}

// ---------------- one irrep-block GEMM (device) ----------------
template<int D, int M, int ROWS, int NU, int WR, int WC>
__device__ __forceinline__
void run_mma(char* smraw,
             const float* __restrict__ x, const float* __restrict__ wt,
             float* __restrict__ out, int n0, int nrows, int xo, int wo, int moff)
{
    constexpr int BK  = 16;
    constexpr int TR  = ROWS / WR, TC = M / WC;
    constexpr int MR  = TR / 16,   MC = TC / 8;
    static_assert(WR * WC == 8 && MR >= 1 && (MC % 2) == 0, "warp grid");
    constexpr int SA  = BK + 8;
    constexpr int SB  = M + 8;
    constexpr int KT  = M / BK;
    constexpr int PT  = 256 / ROWS;
    constexpr int EPT = BK / PT;
    constexpr int NP  = EPT / 2;
    static_assert(EPT % 4 == 0, "wt vec4");

    typedef __nv_bfloat16 bf;
    bf (*As)[2][ROWS][SA] = reinterpret_cast<bf (*)[2][ROWS][SA]>(smraw);
    constexpr uint32_t AS_BYTES = 2u * 2u * ROWS * SA * 2u;
    bf (*Bs)[2][BK][SB] = reinterpret_cast<bf (*)[2][BK][SB]>(smraw + AS_BYTES);

    const int tid = threadIdx.x, lane = tid & 31, wid = tid >> 5;
    const int warpR = wid % WR, warpC = wid / WR;
    const int rw0 = warpR * TR, c0w = warpC * TC;
    const float inv_m = 1.0f / (float)M;

    const int rfill = tid / PT;
    const int kbase = (tid % PT) * EPT;
    const int nl_f = rfill / D, i_f = rfill - nl_f * D;
    const bool fvalid = (rfill < NU * D) && ((n0 + nl_f) < nrows);
    const float* xrow = x  + (size_t)(n0 + nl_f) * DIM_  + xo + i_f;
    const float* wrow = wt + (size_t)(n0 + nl_f) * WNUM_ + wo;

    const uint32_t smA = (uint32_t)__cvta_generic_to_shared(&(*As)[0][0][0]) -
                         0; // base of As[0]
    const uint32_t smB = (uint32_t)__cvta_generic_to_shared(&(*Bs)[0][0][0]);
    constexpr uint32_t PS_A = ROWS * SA * 2, BS_A = 2 * PS_A;
    constexpr uint32_t PS_B = BK * SB * 2,   BS_B = 2 * PS_B;

    const uint32_t aAddr0 = smA +
        (uint32_t)(((rw0 + (lane & 15)) * SA + ((lane >> 4) << 3)) * 2);
    const int bg = lane >> 3;
    const uint32_t bAddr0 = smB +
        (uint32_t)(((((bg & 1) << 3) + (lane & 7)) * SB + c0w + ((bg >> 1) << 3)) * 2);

    float acc[MR][MC][4];
#pragma unroll
    for (int a = 0; a < MR; ++a)
#pragma unroll
        for (int b = 0; b < MC; ++b)
#pragma unroll
            for (int c = 0; c < 4; ++c) acc[a][b][c] = 0.0f;

    float xr[EPT], wr[EPT];

    auto ld_regs = [&](int k0) {
        if (fvalid) {
            if constexpr (D == 1) {
                *reinterpret_cast<float4*>(xr) =
                    *reinterpret_cast<const float4*>(xrow + k0 + kbase);
            } else {
#pragma unroll
                for (int j = 0; j < EPT; ++j)
                    xr[j] = xrow[(size_t)(k0 + kbase + j) * D];
            }
#pragma unroll
            for (int v = 0; v < EPT / 4; ++v)
                reinterpret_cast<float4*>(wr)[v] =
                    *reinterpret_cast<const float4*>(wrow + k0 + kbase + 4 * v);
        } else {
#pragma unroll
            for (int j = 0; j < EPT; ++j) { xr[j] = 0.0f; wr[j] = 0.0f; }
        }
    };

    auto st_as = [&](int buf) {
        uint32_t hh[NP], ll[NP];
#pragma unroll
        for (int p = 0; p < NP; ++p) {
            float s0 = xr[2 * p]     * (wr[2 * p]     * inv_m);
            float s1 = xr[2 * p + 1] * (wr[2 * p + 1] * inv_m);
            split2(s0, s1, hh[p], ll[p]);
        }
        ull* dh = reinterpret_cast<ull*>(&(*(As + buf))[0][rfill][kbase]);
        ull* dl = reinterpret_cast<ull*>(&(*(As + buf))[1][rfill][kbase]);
#pragma unroll
        for (int q = 0; q < NP / 2; ++q) {
            dh[q] = (ull)hh[2 * q] | ((ull)hh[2 * q + 1] << 32);
            dl[q] = (ull)ll[2 * q] | ((ull)ll[2 * q + 1] << 32);
        }
    };

    auto ld_bs = [&](int k0, int buf) {
        constexpr int SEGS = M / 8;
        constexpr int CHT  = 2 * BK * SEGS;
        const char* gsrc = reinterpret_cast<const char*>(g_bsplit);
#pragma unroll
        for (int c = tid; c < CHT; c += 256) {
            int plane = c / (BK * SEGS);
            int rem   = c - plane * (BK * SEGS);
            int k     = rem / SEGS;
            int sg    = rem - k * SEGS;
            uint32_t dst = smB + (uint32_t)buf * BS_B + (uint32_t)plane * PS_B
                         + (uint32_t)((k * SB + sg * 8) * 2);
            const char* src = gsrc +
                (size_t)(plane * 87040 + moff + (k0 + k) * M + sg * 8) * 2;
            cp_async16(dst, src);
        }
    };

    auto compute = [&](int buf) {
        uint32_t ah[MR][4], al[MR][4];
#pragma unroll
        for (int mr = 0; mr < MR; ++mr) {
            uint32_t a = aAddr0 + (uint32_t)buf * BS_A + (uint32_t)(mr * 16 * SA * 2);
            ldsm4(ah[mr], a);
            ldsm4(al[mr], a + PS_A);
        }
#pragma unroll
        for (int mc2 = 0; mc2 < MC / 2; ++mc2) {
            uint32_t b = bAddr0 + (uint32_t)buf * BS_B + (uint32_t)(mc2 * 32);
            uint32_t bh[4], bl[4];
            ldsm4t(bh, b);
            ldsm4t(bl, b + PS_B);
#pragma unroll
            for (int mr = 0; mr < MR; ++mr) {
                mma16816(acc[mr][2 * mc2],     ah[mr], bh[0], bh[1]);
                mma16816(acc[mr][2 * mc2],     ah[mr], bl[0], bl[1]);
                mma16816(acc[mr][2 * mc2],     al[mr], bh[0], bh[1]);
                mma16816(acc[mr][2 * mc2 + 1], ah[mr], bh[2], bh[3]);
                mma16816(acc[mr][2 * mc2 + 1], ah[mr], bl[2], bl[3]);
                mma16816(acc[mr][2 * mc2 + 1], al[mr], bh[2], bh[3]);
            }
        }
    };

    ld_regs(0);
    ld_bs(0, 0);
    cp_commit();
    st_as(0);
    cp_wait0();
    __syncthreads();

#pragma unroll 1
    for (int t = 0; t < KT; ++t) {
        const int cur = t & 1;
        if (t + 1 < KT) {
            ld_regs((t + 1) * BK);
            ld_bs((t + 1) * BK, cur ^ 1);
            cp_commit();
        }
        compute(cur);
        if (t + 1 < KT) {
            st_as(cur ^ 1);
            cp_wait0();
        }
        __syncthreads();
    }

#pragma unroll
    for (int mr = 0; mr < MR; ++mr) {
#pragma unroll
        for (int half = 0; half < 2; ++half) {
            const int r = rw0 + mr * 16 + (lane >> 2) + half * 8;
            if (r < NU * D) {
                const int nl = r / D, i = r - nl * D;
                const int n = n0 + nl;
                if (n < nrows) {
                    float* orow = out + (size_t)n * DIM_ + xo;
#pragma unroll
                    for (int mc = 0; mc < MC; ++mc) {
                        const int cw = c0w + mc * 8 + 2 * (lane & 3);
                        const float v0 = acc[mr][mc][half * 2];
                        const float v1 = acc[mr][mc][half * 2 + 1];
                        if constexpr (D == 1) {
                            *reinterpret_cast<float2*>(orow + cw) = make_float2(v0, v1);
                        } else {
                            orow[(size_t)cw * D + i]       = v0;
                            orow[(size_t)(cw + 1) * D + i] = v1;
                        }
                    }
                }
            }
        }
    }
}

// ---------------- fused dispatch ----------------
// chunk = 1600 rows: b0 x25(NU=64) | b1 x40(NU=40) | b2 x64(NU=25) | b3 x100(NU=16)
#define CHUNK_CTAS 229
#define CHUNK_ROWS 1600
#define SMEM_FUSED 46080   // max branch (b0)

__global__ __launch_bounds__(256, 2)
void tp_mma_fused(const float* __restrict__ x, const float* __restrict__ wt,
                  float* __restrict__ out, int nrows)
{
    __shared__ __align__(16) char smraw[SMEM_FUSED];
    const int bid = blockIdx.x;
    const int r = bid / CHUNK_CTAS;
    const int q = bid - r * CHUNK_CTAS;
    const int base = r * CHUNK_ROWS;

    if (q < 25) {
        // b0: m=256 d=1 | CTA 64x256, warps 2x4
        run_mma<1, 256, 64, 64, 2, 4>(smraw, x, wt, out,
                                      base + q * 64, nrows, 0, 0, 0);
    } else if (q < 65) {
        // b1: m=128 d=3 | CTA 128x128 (120 used), warps 4x2
        run_mma<3, 128, 128, 40, 4, 2>(smraw, x, wt, out,
                                       base + (q - 25) * 40, nrows, 256, 256, 65536);
    } else if (q < 129) {
        // b2: m=64 d=5 | CTA 128x64 (125 used), warps 4x2
        run_mma<5, 64, 128, 25, 4, 2>(smraw, x, wt, out,
                                      base + (q - 65) * 25, nrows, 640, 384, 81920);
    } else {
        // b3: m=32 d=7 | CTA 128x32 (112 used), warps 8x1
        run_mma<7, 32, 128, 16, 8, 1>(smraw, x, wt, out,
                                      base + (q - 129) * 16, nrows, 960, 448, 86016);
    }
}

// ---------------- launch ----------------
extern "C" void kernel_launch(void* const* d_in, const int* in_sizes, int n_in,
                              void* d_out, int out_size)
{
    const float* x  = (const float*)d_in[0];
    const float* wtp = (const float*)d_in[1];
    const float* W0 = (const float*)d_in[2];
    const float* W1 = (const float*)d_in[3];
    const float* W2 = (const float*)d_in[4];
    const float* W3 = (const float*)d_in[5];
    float* out = (float*)d_out;

    const int nrows = in_sizes[0] / DIM_;

    split_b_kernel<<<170, 256>>>(W0, W1, W2, W3);

    const int nchunk = (nrows + CHUNK_ROWS - 1) / CHUNK_ROWS;
    tp_mma_fused<<<nchunk * CHUNK_CTAS, 256>>>(x, wtp, out, nrows);
}

// round 12
// speedup vs baseline: 1.9846x; 1.0389x over previous
#include <cuda_runtime.h>
#include <cuda_bf16.h>
#include <cstdint>

// out[n,w,i] = (1/m) * sum_u x[n,u,i] * weight[n,u] * W[u,w]
// Irreps: 256x0e + 128x1o + 64x2e + 32x3o ; DIM=1184, WNUM=480
// R12: fused mma.sync bf16 3-term split + 3-stage cp.async ring for x/wt/B.

#define DIM_ 1184
#define WNUM_ 480
typedef unsigned long long ull;

__device__ __align__(16) __nv_bfloat16 g_bsplit[2 * 87040];

__device__ __forceinline__ void split2(float s0, float s1, uint32_t& h, uint32_t& l) {
    asm("cvt.rn.satfinite.bf16x2.f32 %0, %1, %2;" : "=r"(h) : "f"(s1), "f"(s0));
    float h0 = __uint_as_float(h << 16);
    float h1 = __uint_as_float(h & 0xffff0000u);
    asm("cvt.rn.satfinite.bf16x2.f32 %0, %1, %2;" : "=r"(l) : "f"(s1 - h1), "f"(s0 - h0));
}

__device__ __forceinline__ void cp_async16(uint32_t dst, const void* src) {
    asm volatile("cp.async.cg.shared.global [%0], [%1], 16;" :: "r"(dst), "l"(src));
}
__device__ __forceinline__ void cp_commit() { asm volatile("cp.async.commit_group;"); }
__device__ __forceinline__ void cp_wait1()  { asm volatile("cp.async.wait_group 1;" ::: "memory"); }

__device__ __forceinline__ void ldsm4(uint32_t* r, uint32_t a) {
    asm volatile("ldmatrix.sync.aligned.m8n8.x4.shared.b16 {%0,%1,%2,%3}, [%4];"
                 : "=r"(r[0]), "=r"(r[1]), "=r"(r[2]), "=r"(r[3]) : "r"(a));
}
__device__ __forceinline__ void ldsm4t(uint32_t* r, uint32_t a) {
    asm volatile("ldmatrix.sync.aligned.m8n8.x4.trans.shared.b16 {%0,%1,%2,%3}, [%4];"
                 : "=r"(r[0]), "=r"(r[1]), "=r"(r[2]), "=r"(r[3]) : "r"(a));
}
__device__ __forceinline__ void mma16816(float* c, const uint32_t* a,
                                         uint32_t b0, uint32_t b1) {
    asm volatile(
        "mma.sync.aligned.m16n8k16.row.col.f32.bf16.bf16.f32 "
        "{%0,%1,%2,%3}, {%4,%5,%6,%7}, {%8,%9}, {%0,%1,%2,%3};"
        : "+f"(c[0]), "+f"(c[1]), "+f"(c[2]), "+f"(c[3])
        : "r"(a[0]), "r"(a[1]), "r"(a[2]), "r"(a[3]), "r"(b0), "r"(b1));
}

// ---------------- B split precompute ----------------
__global__ void split_b_kernel(const float* __restrict__ W0, const float* __restrict__ W1,
                               const float* __restrict__ W2, const float* __restrict__ W3)
{
    int idx = blockIdx.x * blockDim.x + threadIdx.x;
    if (idx >= 43520) return;
    int e = idx * 2;
    const float* src; int off;
    if (e < 65536)      { src = W0; off = e; }
    else if (e < 81920) { src = W1; off = e - 65536; }
    else if (e < 86016) { src = W2; off = e - 81920; }
    else                { src = W3; off = e - 86016; }
    float2 v = *reinterpret_cast<const float2*>(src + off);
    uint32_t h, l;
    split2(v.x, v.y, h, l);
    reinterpret_cast<uint32_t*>(g_bsplit)[idx] = h;
    reinterpret_cast<uint32_t*>(g_bsplit)[43520 + idx] = l;
}

// ---------------- one irrep-block GEMM (device) ----------------
template<int D, int M, int ROWS, int NU, int WR, int WC>
__device__ __forceinline__
void run_mma(char* sm,
             const float* __restrict__ x, const float* __restrict__ wt,
             float* __restrict__ out, int n0, int nrows, int xo, int wo, int moff)
{
    constexpr int STG = 3;
    constexpr int BK  = 16;
    constexpr int TR  = ROWS / WR, TC = M / WC;
    constexpr int MR  = TR / 16,   MC = TC / 8;
    static_assert(WR * WC == 8 && MR >= 1 && (MC % 2) == 0, "warp grid");
    constexpr int SA  = BK + 8;              // As row stride (bf16)
    constexpr int SB  = M + 8;               // Bs row stride (bf16)
    constexpr int KT  = M / BK;
    constexpr int PT  = 256 / ROWS;
    constexpr int EPT = BK / PT;
    constexpr int NP  = EPT / 2;
    constexpr int XROW = BK * D + 4;         // floats
    constexpr int WROW = BK + 4;             // floats

    constexpr uint32_t AS_BYTES = 2u * 2u * ROWS * SA * 2u;
    constexpr uint32_t PS_A     = (uint32_t)ROWS * SA * 2u;
    constexpr uint32_t BS_A     = 2u * PS_A;
    constexpr uint32_t BPLANE   = (uint32_t)BK * SB * 2u;
    constexpr uint32_t BSTAGE   = 2u * BPLANE;
    constexpr uint32_t XSTAGE   = (uint32_t)NU * XROW * 4u;
    constexpr uint32_t WSTAGE   = (uint32_t)NU * WROW * 4u;

    typedef __nv_bfloat16 bf;
    bf*    As = reinterpret_cast<bf*>(sm);
    float* Xs = reinterpret_cast<float*>(sm + AS_BYTES + STG * BSTAGE);
    float* Wsm = reinterpret_cast<float*>(sm + AS_BYTES + STG * BSTAGE + STG * XSTAGE);

    const int tid = threadIdx.x, lane = tid & 31, wid = tid >> 5;
    const int warpR = wid % WR, warpC = wid / WR;
    const int rw0 = warpR * TR, c0w = warpC * TC;
    const float inv_m = 1.0f / (float)M;

    const int rfill = tid / PT;
    const int kbase = (tid % PT) * EPT;
    const int nl_f = rfill / D, i_f = rfill - nl_f * D;
    const bool fvalid = (rfill < NU * D) && ((n0 + nl_f) < nrows);

    const uint32_t smA = (uint32_t)__cvta_generic_to_shared(sm);
    const uint32_t smB = smA + AS_BYTES;
    const uint32_t smX = smB + STG * BSTAGE;
    const uint32_t smW = smX + STG * XSTAGE;

    const uint32_t aAddr0 = smA +
        (uint32_t)(((rw0 + (lane & 15)) * SA + ((lane >> 4) << 3)) * 2);
    const int bg = lane >> 3;
    const uint32_t bAddr0 = smB +
        (uint32_t)(((((bg & 1) << 3) + (lane & 7)) * SB + c0w + ((bg >> 1) << 3)) * 2);

    float acc[MR][MC][4];
#pragma unroll
    for (int a = 0; a < MR; ++a)
#pragma unroll
        for (int b = 0; b < MC; ++b)
#pragma unroll
            for (int c = 0; c < 4; ++c) acc[a][b][c] = 0.0f;

    // ---- issue one tile's cp.async (no commit) ----
    auto issue_tile = [&](int t) {
        const int slot = t % STG;
        const int u0 = t * BK;
        // B planes
        constexpr int BCH = 2 * BK * (M / 8);
        const char* gb = reinterpret_cast<const char*>(g_bsplit);
#pragma unroll 2
        for (int c = tid; c < BCH; c += 256) {
            int plane = c / (BK * (M / 8));
            int rem   = c - plane * (BK * (M / 8));
            int k     = rem / (M / 8);
            int sg    = rem - k * (M / 8);
            uint32_t dst = smB + (uint32_t)slot * BSTAGE + (uint32_t)plane * BPLANE
                         + (uint32_t)((k * SB + sg * 8) * 2);
            const char* src = gb + (size_t)(plane * 87040 + moff + (u0 + k) * M + sg * 8) * 2;
            cp_async16(dst, src);
        }
        // x raw
        constexpr int XCH = BK * D / 4;
#pragma unroll 2
        for (int c = tid; c < NU * XCH; c += 256) {
            int row = c / XCH, sg = c - row * XCH;
            if (n0 + row < nrows) {
                uint32_t dst = smX + (uint32_t)slot * XSTAGE
                             + (uint32_t)((row * XROW + sg * 4) * 4);
                const float* src = x + (size_t)(n0 + row) * DIM_ + xo + u0 * D + sg * 4;
                cp_async16(dst, src);
            }
        }
        // wt raw
        constexpr int WCH = BK / 4;
#pragma unroll 1
        for (int c = tid; c < NU * WCH; c += 256) {
            int row = c / WCH, sg = c - row * WCH;
            if (n0 + row < nrows) {
                uint32_t dst = smW + (uint32_t)slot * WSTAGE
                             + (uint32_t)((row * WROW + sg * 4) * 4);
                const float* src = wt + (size_t)(n0 + row) * WNUM_ + wo + u0 + sg * 4;
                cp_async16(dst, src);
            }
        }
    };

    // ---- split one tile from raw smem into As[t&1] ----
    auto split_tile = [&](int t) {
        const int slot = t % STG;
        uint32_t hh[NP], ll[NP];
        if (fvalid) {
            const float* xr = Xs + (size_t)slot * (NU * XROW) + nl_f * XROW + i_f;
            const float* wr = Wsm + (size_t)slot * (NU * WROW) + nl_f * WROW + kbase;
#pragma unroll
            for (int p = 0; p < NP; ++p) {
                float w0 = wr[2 * p] * inv_m, w1 = wr[2 * p + 1] * inv_m;
                float s0 = xr[(kbase + 2 * p) * D]     * w0;
                float s1 = xr[(kbase + 2 * p + 1) * D] * w1;
                split2(s0, s1, hh[p], ll[p]);
            }
        } else {
#pragma unroll
            for (int p = 0; p < NP; ++p) { hh[p] = 0; ll[p] = 0; }
        }
        const int buf = t & 1;
        ull* dh = reinterpret_cast<ull*>(As + (size_t)(buf * 2 + 0) * ROWS * SA
                                         + rfill * SA + kbase);
        ull* dl = reinterpret_cast<ull*>(As + (size_t)(buf * 2 + 1) * ROWS * SA
                                         + rfill * SA + kbase);
#pragma unroll
        for (int q = 0; q < NP / 2; ++q) {
            dh[q] = (ull)hh[2 * q] | ((ull)hh[2 * q + 1] << 32);
            dl[q] = (ull)ll[2 * q] | ((ull)ll[2 * q + 1] << 32);
        }
    };

    auto compute = [&](int t) {
        const int buf = t & 1, slot = t % STG;
        uint32_t ah[MR][4], al[MR][4];
#pragma unroll
        for (int mr = 0; mr < MR; ++mr) {
            uint32_t a = aAddr0 + (uint32_t)buf * BS_A + (uint32_t)(mr * 16 * SA * 2);
            ldsm4(ah[mr], a);
            ldsm4(al[mr], a + PS_A);
        }
#pragma unroll
        for (int mc2 = 0; mc2 < MC / 2; ++mc2) {
            uint32_t b = bAddr0 + (uint32_t)slot * BSTAGE + (uint32_t)(mc2 * 32);
            uint32_t bh[4], bl[4];
            ldsm4t(bh, b);
            ldsm4t(bl, b + BPLANE);
#pragma unroll
            for (int mr = 0; mr < MR; ++mr) {
                mma16816(acc[mr][2 * mc2],     ah[mr], bh[0], bh[1]);
                mma16816(acc[mr][2 * mc2],     ah[mr], bl[0], bl[1]);
                mma16816(acc[mr][2 * mc2],     al[mr], bh[0], bh[1]);
                mma16816(acc[mr][2 * mc2 + 1], ah[mr], bh[2], bh[3]);
                mma16816(acc[mr][2 * mc2 + 1], ah[mr], bl[2], bl[3]);
                mma16816(acc[mr][2 * mc2 + 1], al[mr], bh[2], bh[3]);
            }
        }
    };

    // ---- pipeline: STG-1 tiles in flight ----
#pragma unroll
    for (int t = 0; t < STG - 1; ++t) {
        if (t < KT) issue_tile(t);
        cp_commit();
    }
#pragma unroll 1
    for (int t = 0; t < KT; ++t) {
        cp_wait1();                 // tile t's group complete
        __syncthreads();            // raw(t) visible; Bs slot (t-1) free
        if (t + STG - 1 < KT) issue_tile(t + STG - 1);
        cp_commit();                // empty group when nothing issued
        split_tile(t);
        __syncthreads();            // As[t&1] ready
        compute(t);
    }

    // ---- epilogue: direct STG from fragments ----
#pragma unroll
    for (int mr = 0; mr < MR; ++mr) {
#pragma unroll
        for (int half = 0; half < 2; ++half) {
            const int r = rw0 + mr * 16 + (lane >> 2) + half * 8;
            if (r < NU * D) {
                const int nl = r / D, i = r - nl * D;
                const int n = n0 + nl;
                if (n < nrows) {
                    float* orow = out + (size_t)n * DIM_ + xo;
#pragma unroll
                    for (int mc = 0; mc < MC; ++mc) {
                        const int cw = c0w + mc * 8 + 2 * (lane & 3);
                        const float v0 = acc[mr][mc][half * 2];
                        const float v1 = acc[mr][mc][half * 2 + 1];
                        if constexpr (D == 1) {
                            *reinterpret_cast<float2*>(orow + cw) = make_float2(v0, v1);
                        } else {
                            orow[(size_t)cw * D + i]       = v0;
                            orow[(size_t)(cw + 1) * D + i] = v1;
                        }
                    }
                }
            }
        }
    }
}

// ---------------- fused dispatch ----------------
// chunk = 1600 rows: b0 x25(NU=64) | b1 x40(NU=40) | b2 x64(NU=25) | b3 x100(NU=16)
#define CHUNK_CTAS 229
#define CHUNK_ROWS 1600
#define SMEM_DYN 94208

__global__ __launch_bounds__(256, 2)
void tp_mma_fused(const float* __restrict__ x, const float* __restrict__ wt,
                  float* __restrict__ out, int nrows)
{
    extern __shared__ __align__(16) char smraw[];
    const int bid = blockIdx.x;
    const int r = bid / CHUNK_CTAS;
    const int q = bid - r * CHUNK_CTAS;
    const int base = r * CHUNK_ROWS;

    if (q < 25) {
        run_mma<1, 256, 64, 64, 2, 4>(smraw, x, wt, out,
                                      base + q * 64, nrows, 0, 0, 0);
    } else if (q < 65) {
        run_mma<3, 128, 128, 40, 4, 2>(smraw, x, wt, out,
                                       base + (q - 25) * 40, nrows, 256, 256, 65536);
    } else if (q < 129) {
        run_mma<5, 64, 128, 25, 4, 2>(smraw, x, wt, out,
                                      base + (q - 65) * 25, nrows, 640, 384, 81920);
    } else {
        run_mma<7, 32, 128, 16, 8, 1>(smraw, x, wt, out,
                                      base + (q - 129) * 16, nrows, 960, 448, 86016);
    }
}

// ---------------- launch ----------------
extern "C" void kernel_launch(void* const* d_in, const int* in_sizes, int n_in,
                              void* d_out, int out_size)
{
    const float* x  = (const float*)d_in[0];
    const float* wtp = (const float*)d_in[1];
    const float* W0 = (const float*)d_in[2];
    const float* W1 = (const float*)d_in[3];
    const float* W2 = (const float*)d_in[4];
    const float* W3 = (const float*)d_in[5];
    float* out = (float*)d_out;

    const int nrows = in_sizes[0] / DIM_;

    static int attr_set = 0;
    if (!attr_set) {
        cudaFuncSetAttribute(tp_mma_fused,
                             cudaFuncAttributeMaxDynamicSharedMemorySize, SMEM_DYN);
        attr_set = 1;
    }

    split_b_kernel<<<170, 256>>>(W0, W1, W2, W3);

    const int nchunk = (nrows + CHUNK_ROWS - 1) / CHUNK_ROWS;
    tp_mma_fused<<<nchunk * CHUNK_CTAS, 256, SMEM_DYN>>>(x, wtp, out, nrows);
}

// round 13
// speedup vs baseline: 2.0152x; 1.0154x over previous
#include <cuda_runtime.h>
#include <cuda_bf16.h>
#include <cstdint>

// out[n,w,i] = (1/m) * sum_u x[n,u,i] * weight[n,u] * W[u,w]
// Irreps: 256x0e + 128x1o + 64x2e + 32x3o ; DIM=1184, WNUM=480
// R13: break mma RAW chains (term-major order), fold 1/m into B planes
//      (exact: m are powers of 2), hoisted cp.async src pointers.

#define DIM_ 1184
#define WNUM_ 480
typedef unsigned long long ull;

__device__ __align__(16) __nv_bfloat16 g_bsplit[2 * 87040];

__device__ __forceinline__ void split2(float s0, float s1, uint32_t& h, uint32_t& l) {
    asm("cvt.rn.satfinite.bf16x2.f32 %0, %1, %2;" : "=r"(h) : "f"(s1), "f"(s0));
    float h0 = __uint_as_float(h << 16);
    float h1 = __uint_as_float(h & 0xffff0000u);
    asm("cvt.rn.satfinite.bf16x2.f32 %0, %1, %2;" : "=r"(l) : "f"(s1 - h1), "f"(s0 - h0));
}

__device__ __forceinline__ void cp_async16(uint32_t dst, const void* src) {
    asm volatile("cp.async.cg.shared.global [%0], [%1], 16;" :: "r"(dst), "l"(src));
}
__device__ __forceinline__ void cp_commit() { asm volatile("cp.async.commit_group;"); }
__device__ __forceinline__ void cp_wait1()  { asm volatile("cp.async.wait_group 1;" ::: "memory"); }

__device__ __forceinline__ void ldsm4(uint32_t* r, uint32_t a) {
    asm volatile("ldmatrix.sync.aligned.m8n8.x4.shared.b16 {%0,%1,%2,%3}, [%4];"
                 : "=r"(r[0]), "=r"(r[1]), "=r"(r[2]), "=r"(r[3]) : "r"(a));
}
__device__ __forceinline__ void ldsm4t(uint32_t* r, uint32_t a) {
    asm volatile("ldmatrix.sync.aligned.m8n8.x4.trans.shared.b16 {%0,%1,%2,%3}, [%4];"
                 : "=r"(r[0]), "=r"(r[1]), "=r"(r[2]), "=r"(r[3]) : "r"(a));
}
__device__ __forceinline__ void mma16816(float* c, const uint32_t* a,
                                         uint32_t b0, uint32_t b1) {
    asm volatile(
        "mma.sync.aligned.m16n8k16.row.col.f32.bf16.bf16.f32 "
        "{%0,%1,%2,%3}, {%4,%5,%6,%7}, {%8,%9}, {%0,%1,%2,%3};"
        : "+f"(c[0]), "+f"(c[1]), "+f"(c[2]), "+f"(c[3])
        : "r"(a[0]), "r"(a[1]), "r"(a[2]), "r"(a[3]), "r"(b0), "r"(b1));
}

// ---------------- B split precompute (scaled by 1/m, exact pow2) ----------------
__global__ void split_b_kernel(const float* __restrict__ W0, const float* __restrict__ W1,
                               const float* __restrict__ W2, const float* __restrict__ W3)
{
    int idx = blockIdx.x * blockDim.x + threadIdx.x;
    if (idx >= 43520) return;
    int e = idx * 2;
    const float* src; int off; float sc;
    if (e < 65536)      { src = W0; off = e;         sc = 1.0f / 256.0f; }
    else if (e < 81920) { src = W1; off = e - 65536; sc = 1.0f / 128.0f; }
    else if (e < 86016) { src = W2; off = e - 81920; sc = 1.0f / 64.0f; }
    else                { src = W3; off = e - 86016; sc = 1.0f / 32.0f; }
    float2 v = *reinterpret_cast<const float2*>(src + off);
    uint32_t h, l;
    split2(v.x * sc, v.y * sc, h, l);
    reinterpret_cast<uint32_t*>(g_bsplit)[idx] = h;
    reinterpret_cast<uint32_t*>(g_bsplit)[43520 + idx] = l;
}

// ---------------- one irrep-block GEMM (device) ----------------
template<int D, int M, int ROWS, int NU, int WR, int WC>
__device__ __forceinline__
void run_mma(char* sm,
             const float* __restrict__ x, const float* __restrict__ wt,
             float* __restrict__ out, int n0, int nrows, int xo, int wo, int moff)
{
    constexpr int STG = 3;
    constexpr int BK  = 16;
    constexpr int TR  = ROWS / WR, TC = M / WC;
    constexpr int MR  = TR / 16,   MC = TC / 8;
    static_assert(WR * WC == 8 && MR >= 1 && (MC % 2) == 0, "warp grid");
    constexpr int SA  = BK + 8;
    constexpr int SB  = M + 8;
    constexpr int KT  = M / BK;
    constexpr int PT  = 256 / ROWS;
    constexpr int EPT = BK / PT;
    constexpr int NP  = EPT / 2;
    constexpr int XROW = BK * D + 4;         // floats
    constexpr int WROW = BK + 4;             // floats

    constexpr uint32_t AS_BYTES = 2u * 2u * ROWS * SA * 2u;
    constexpr uint32_t PS_A     = (uint32_t)ROWS * SA * 2u;
    constexpr uint32_t BS_A     = 2u * PS_A;
    constexpr uint32_t BPLANE   = (uint32_t)BK * SB * 2u;
    constexpr uint32_t BSTAGE   = 2u * BPLANE;
    constexpr uint32_t XSTAGE   = (uint32_t)NU * XROW * 4u;
    constexpr uint32_t WSTAGE   = (uint32_t)NU * WROW * 4u;

    typedef __nv_bfloat16 bf;
    bf*    As  = reinterpret_cast<bf*>(sm);
    float* Xs  = reinterpret_cast<float*>(sm + AS_BYTES + STG * BSTAGE);
    float* Wsm = reinterpret_cast<float*>(sm + AS_BYTES + STG * BSTAGE + STG * XSTAGE);

    const int tid = threadIdx.x, lane = tid & 31, wid = tid >> 5;
    const int warpR = wid % WR, warpC = wid / WR;
    const int rw0 = warpR * TR, c0w = warpC * TC;

    const int rfill = tid / PT;
    const int kbase = (tid % PT) * EPT;
    const int nl_f = rfill / D, i_f = rfill - nl_f * D;
    const bool fvalid = (rfill < NU * D) && ((n0 + nl_f) < nrows);

    const uint32_t smA = (uint32_t)__cvta_generic_to_shared(sm);
    const uint32_t smB = smA + AS_BYTES;
    const uint32_t smX = smB + STG * BSTAGE;
    const uint32_t smW = smX + STG * XSTAGE;

    const uint32_t aAddr0 = smA +
        (uint32_t)(((rw0 + (lane & 15)) * SA + ((lane >> 4) << 3)) * 2);
    const int bg = lane >> 3;
    const uint32_t bAddr0 = smB +
        (uint32_t)(((((bg & 1) << 3) + (lane & 7)) * SB + c0w + ((bg >> 1) << 3)) * 2);

    // ---- hoisted cp.async chunk descriptors ----
    constexpr int BCH = 2 * BK * (M / 8);
    constexpr int NBC = (BCH + 255) / 256;
    constexpr int XCHR = BK * D / 4;
    constexpr int XCH = NU * XCHR;
    constexpr int NXC = (XCH + 255) / 256;
    constexpr int WCH = NU * (BK / 4);
    constexpr int NWC = 1;

    const char* bsrcp[NBC]; uint32_t bdsto[NBC]; bool bokk[NBC];
    {
        const char* gb = reinterpret_cast<const char*>(g_bsplit);
#pragma unroll
        for (int i = 0; i < NBC; ++i) {
            int c = tid + i * 256;
            bokk[i] = (c < BCH);
            int cc = bokk[i] ? c : 0;
            int plane = cc / (BK * (M / 8));
            int rem   = cc - plane * (BK * (M / 8));
            int k     = rem / (M / 8);
            int sg    = rem - k * (M / 8);
            bdsto[i] = smB + (uint32_t)plane * BPLANE + (uint32_t)((k * SB + sg * 8) * 2);
            bsrcp[i] = gb + (size_t)(plane * 87040 + moff + k * M + sg * 8) * 2;
        }
    }
    const float* xsrcp[NXC]; uint32_t xdsto[NXC]; bool xokk[NXC];
    {
#pragma unroll
        for (int i = 0; i < NXC; ++i) {
            int c = tid + i * 256;
            bool ok = (c < XCH);
            int cc = ok ? c : 0;
            int row = cc / XCHR, sg = cc - row * XCHR;
            xokk[i] = ok && ((n0 + row) < nrows);
            xdsto[i] = smX + (uint32_t)((row * XROW + sg * 4) * 4);
            xsrcp[i] = x + (size_t)(n0 + row) * DIM_ + xo + sg * 4;
        }
    }
    const float* wsrcp[NWC]; uint32_t wdsto[NWC]; bool wokk[NWC];
    {
#pragma unroll
        for (int i = 0; i < NWC; ++i) {
            int c = tid + i * 256;
            bool ok = (c < WCH);
            int cc = ok ? c : 0;
            int row = cc / (BK / 4), sg = cc - row * (BK / 4);
            wokk[i] = ok && ((n0 + row) < nrows);
            wdsto[i] = smW + (uint32_t)((row * WROW + sg * 4) * 4);
            wsrcp[i] = wt + (size_t)(n0 + row) * WNUM_ + wo + sg * 4;
        }
    }

    float acc[MR][MC][4];
#pragma unroll
    for (int a = 0; a < MR; ++a)
#pragma unroll
        for (int b = 0; b < MC; ++b)
#pragma unroll
            for (int c = 0; c < 4; ++c) acc[a][b][c] = 0.0f;

    auto issue_tile = [&](int t) {
        const uint32_t so_b = (uint32_t)(t % STG) * BSTAGE;
        const uint32_t so_x = (uint32_t)(t % STG) * XSTAGE;
        const uint32_t so_w = (uint32_t)(t % STG) * WSTAGE;
#pragma unroll
        for (int i = 0; i < NBC; ++i) {
            if (bokk[i]) cp_async16(bdsto[i] + so_b, bsrcp[i]);
            bsrcp[i] += (size_t)BK * M * 2;
        }
#pragma unroll
        for (int i = 0; i < NXC; ++i) {
            if (xokk[i]) cp_async16(xdsto[i] + so_x, xsrcp[i]);
            xsrcp[i] += BK * D;
        }
#pragma unroll
        for (int i = 0; i < NWC; ++i) {
            if (wokk[i]) cp_async16(wdsto[i] + so_w, wsrcp[i]);
            wsrcp[i] += BK;
        }
    };

    auto split_tile = [&](int t) {
        const int slot = t % STG;
        uint32_t hh[NP], ll[NP];
        if (fvalid) {
            const float* xr = Xs + (size_t)slot * (NU * XROW) + nl_f * XROW + i_f;
            const float* wr = Wsm + (size_t)slot * (NU * WROW) + nl_f * WROW + kbase;
            if constexpr (D == 1) {
                float4 xv = *reinterpret_cast<const float4*>(xr + kbase);
                float4 wv = *reinterpret_cast<const float4*>(wr);
                split2(xv.x * wv.x, xv.y * wv.y, hh[0], ll[0]);
                split2(xv.z * wv.z, xv.w * wv.w, hh[1], ll[1]);
            } else {
                alignas(16) float w[EPT];
#pragma unroll
                for (int v = 0; v < EPT / 4; ++v)
                    reinterpret_cast<float4*>(w)[v] =
                        *reinterpret_cast<const float4*>(wr + 4 * v);
#pragma unroll
                for (int p = 0; p < NP; ++p) {
                    float s0 = xr[(kbase + 2 * p) * D]     * w[2 * p];
                    float s1 = xr[(kbase + 2 * p + 1) * D] * w[2 * p + 1];
                    split2(s0, s1, hh[p], ll[p]);
                }
            }
        } else {
#pragma unroll
            for (int p = 0; p < NP; ++p) { hh[p] = 0; ll[p] = 0; }
        }
        const int buf = t & 1;
        ull* dh = reinterpret_cast<ull*>(As + (size_t)(buf * 2 + 0) * ROWS * SA
                                         + rfill * SA + kbase);
        ull* dl = reinterpret_cast<ull*>(As + (size_t)(buf * 2 + 1) * ROWS * SA
                                         + rfill * SA + kbase);
#pragma unroll
        for (int q = 0; q < NP / 2; ++q) {
            dh[q] = (ull)hh[2 * q] | ((ull)hh[2 * q + 1] << 32);
            dl[q] = (ull)ll[2 * q] | ((ull)ll[2 * q + 1] << 32);
        }
    };

    // term-major mma order: acc reuse distance = 2*MR mmas (RAW chain broken)
    auto compute = [&](int t) {
        const int buf = t & 1, slot = t % STG;
        uint32_t ah[MR][4], al[MR][4];
#pragma unroll
        for (int mr = 0; mr < MR; ++mr) {
            uint32_t a = aAddr0 + (uint32_t)buf * BS_A + (uint32_t)(mr * 16 * SA * 2);
            ldsm4(ah[mr], a);
            ldsm4(al[mr], a + PS_A);
        }
#pragma unroll
        for (int mc2 = 0; mc2 < MC / 2; ++mc2) {
            uint32_t b = bAddr0 + (uint32_t)slot * BSTAGE + (uint32_t)(mc2 * 32);
            uint32_t bh[4], bl[4];
            ldsm4t(bh, b);
            ldsm4t(bl, b + BPLANE);
#pragma unroll
            for (int mr = 0; mr < MR; ++mr) {          // term hh
                mma16816(acc[mr][2 * mc2],     ah[mr], bh[0], bh[1]);
                mma16816(acc[mr][2 * mc2 + 1], ah[mr], bh[2], bh[3]);
            }
#pragma unroll
            for (int mr = 0; mr < MR; ++mr) {          // term hl
                mma16816(acc[mr][2 * mc2],     ah[mr], bl[0], bl[1]);
                mma16816(acc[mr][2 * mc2 + 1], ah[mr], bl[2], bl[3]);
            }
#pragma unroll
            for (int mr = 0; mr < MR; ++mr) {          // term lh
                mma16816(acc[mr][2 * mc2],     al[mr], bh[0], bh[1]);
                mma16816(acc[mr][2 * mc2 + 1], al[mr], bh[2], bh[3]);
            }
        }
    };

    // ---- pipeline ----
#pragma unroll
    for (int t = 0; t < STG - 1; ++t) {
        if (t < KT) issue_tile(t);
        cp_commit();
    }
#pragma unroll 1
    for (int t = 0; t < KT; ++t) {
        cp_wait1();
        __syncthreads();
        if (t + STG - 1 < KT) issue_tile(t + STG - 1);
        cp_commit();
        split_tile(t);
        __syncthreads();
        compute(t);
    }

    // ---- epilogue ----
#pragma unroll
    for (int mr = 0; mr < MR; ++mr) {
#pragma unroll
        for (int half = 0; half < 2; ++half) {
            const int r = rw0 + mr * 16 + (lane >> 2) + half * 8;
            if (r < NU * D) {
                const int nl = r / D, i = r - nl * D;
                const int n = n0 + nl;
                if (n < nrows) {
                    float* orow = out + (size_t)n * DIM_ + xo;
#pragma unroll
                    for (int mc = 0; mc < MC; ++mc) {
                        const int cw = c0w + mc * 8 + 2 * (lane & 3);
                        const float v0 = acc[mr][mc][half * 2];
                        const float v1 = acc[mr][mc][half * 2 + 1];
                        if constexpr (D == 1) {
                            *reinterpret_cast<float2*>(orow + cw) = make_float2(v0, v1);
                        } else {
                            orow[(size_t)cw * D + i]       = v0;
                            orow[(size_t)(cw + 1) * D + i] = v1;
                        }
                    }
                }
            }
        }
    }
}

// ---------------- fused dispatch ----------------
#define CHUNK_CTAS 229
#define CHUNK_ROWS 1600
#define SMEM_DYN 94208

__global__ __launch_bounds__(256, 2)
void tp_mma_fused(const float* __restrict__ x, const float* __restrict__ wt,
                  float* __restrict__ out, int nrows)
{
    extern __shared__ __align__(16) char smraw[];
    const int bid = blockIdx.x;
    const int r = bid / CHUNK_CTAS;
    const int q = bid - r * CHUNK_CTAS;
    const int base = r * CHUNK_ROWS;

    if (q < 25) {
        run_mma<1, 256, 64, 64, 2, 4>(smraw, x, wt, out,
                                      base + q * 64, nrows, 0, 0, 0);
    } else if (q < 65) {
        run_mma<3, 128, 128, 40, 4, 2>(smraw, x, wt, out,
                                       base + (q - 25) * 40, nrows, 256, 256, 65536);
    } else if (q < 129) {
        run_mma<5, 64, 128, 25, 4, 2>(smraw, x, wt, out,
                                      base + (q - 65) * 25, nrows, 640, 384, 81920);
    } else {
        run_mma<7, 32, 128, 16, 8, 1>(smraw, x, wt, out,
                                      base + (q - 129) * 16, nrows, 960, 448, 86016);
    }
}

// ---------------- launch ----------------
extern "C" void kernel_launch(void* const* d_in, const int* in_sizes, int n_in,
                              void* d_out, int out_size)
{
    const float* x  = (const float*)d_in[0];
    const float* wtp = (const float*)d_in[1];
    const float* W0 = (const float*)d_in[2];
    const float* W1 = (const float*)d_in[3];
    const float* W2 = (const float*)d_in[4];
    const float* W3 = (const float*)d_in[5];
    float* out = (float*)d_out;

    const int nrows = in_sizes[0] / DIM_;

    static int attr_set = 0;
    if (!attr_set) {
        cudaFuncSetAttribute(tp_mma_fused,
                             cudaFuncAttributeMaxDynamicSharedMemorySize, SMEM_DYN);
        attr_set = 1;
    }

    split_b_kernel<<<170, 256>>>(W0, W1, W2, W3);

    const int nchunk = (nrows + CHUNK_ROWS - 1) / CHUNK_ROWS;
    tp_mma_fused<<<nchunk * CHUNK_CTAS, 256, SMEM_DYN>>>(x, wtp, out, nrows);
}